// round 3
// baseline (speedup 1.0000x reference)
#include <cuda_runtime.h>
#include <cstdint>

// Problem constants
#define SEQ       32768
#define NT        512
#define START_TAG 510
#define END_TAG   511
#define NEG_FILL  (-10000.0f)

// Launch geometry: 128 persistent CTAs x 128 threads. CTA c owns tags
// j = 4c..4c+3 (one tag per warp); lane owns i-range [16*lane, 16*lane+16).
#define GRIDN 128
#define TPB   128
#define IPL   16

// Traceback segmentation
#define SEGS   128
#define SEGLEN 256   // SEGS * SEGLEN == SEQ

// ---------------------------------------------------------------------------
// Device scratch (static __device__ arrays: allocation-free per harness rules)
// ---------------------------------------------------------------------------
__device__ float              g_alphas[2][NT];          // double-buffered alphas
__device__ unsigned short     g_bp[SEQ][NT];            // backpointers (32 MB)
__device__ unsigned long long g_count;                  // grid-barrier counter
__device__ int                g_best;                   // terminal argmax tag
__device__ unsigned short     g_exit[SEGS][NT];         // per-segment exit map

// Order-preserving float<->uint bijection (exact, monotone)
__device__ __forceinline__ unsigned enc32(float f) {
    unsigned u = __float_as_uint(f);
    return (u & 0x80000000u) ? ~u : (u | 0x80000000u);
}
__device__ __forceinline__ float dec32(unsigned o) {
    unsigned u = (o & 0x80000000u) ? (o & 0x7fffffffu) : ~o;
    return __uint_as_float(u);
}

// ---------------------------------------------------------------------------
// Grid barrier: monotone counter, reset by viterbi_reset each launch.
// Arrive: non-returning release reduction. Wait: acquire spin until n*GRIDN.
// ---------------------------------------------------------------------------
__device__ __forceinline__ void bar_arrive() {
    asm volatile("red.release.gpu.add.u64 [%0], %1;"
                 :: "l"(&g_count), "l"(1ull) : "memory");
}
__device__ __forceinline__ void bar_wait(unsigned long long n) {
    const unsigned long long target = n * (unsigned long long)GRIDN;
    unsigned long long c;
    do {
        asm volatile("ld.acquire.gpu.u64 %0, [%1];"
                     : "=l"(c) : "l"(&g_count) : "memory");
    } while (c < target);
}

__global__ void viterbi_reset() { g_count = 0ull; }

// ---------------------------------------------------------------------------
// Main persistent Viterbi kernel
// ---------------------------------------------------------------------------
__global__ void __launch_bounds__(TPB, 1) viterbi_main(
    const float* __restrict__ unary,   // [SEQ][NT]
    const float* __restrict__ trans,   // [NT][NT]  (tr[j][i])
    float* __restrict__ out, int out_size)
{
    const int tid   = threadIdx.x;
    const int warp  = tid >> 5;
    const int lane  = tid & 31;
    const int cta   = blockIdx.x;
    const int j     = (cta << 2) + warp;   // tag owned by this warp
    const int ibase = lane << 4;           // first source tag for this lane

    // Register-resident transition slice: tr[j][ibase + k]
    float tr[IPL];
    {
        const float4* tp = reinterpret_cast<const float4*>(trans + j * NT + ibase);
#pragma unroll
        for (int q = 0; q < 4; ++q) {
            float4 v = __ldg(tp + q);
            tr[4*q+0] = v.x; tr[4*q+1] = v.y; tr[4*q+2] = v.z; tr[4*q+3] = v.w;
        }
    }

    // alphas0 into buffer 0
    if (lane == 0)
        __stcg(&g_alphas[0][j], (j == START_TAG) ? 0.0f : NEG_FILL);

    float ucur = 0.0f, unext = 0.0f;
    if (lane == 0) ucur = __ldg(unary + j);   // u[0][j]

    unsigned long long nbar = 0;

    // Barrier 0: publish initial alphas
    __syncthreads();
    if (tid == 0) bar_arrive();
    nbar++;
    if (tid == 0) bar_wait(nbar);
    __syncthreads();

    // Load alphas for step 0
    float a[IPL];
    {
        const float4* ap = reinterpret_cast<const float4*>(&g_alphas[0][ibase]);
#pragma unroll
        for (int q = 0; q < 4; ++q) {
            float4 v = __ldcg(ap + q);
            a[4*q+0]=v.x; a[4*q+1]=v.y; a[4*q+2]=v.z; a[4*q+3]=v.w;
        }
    }

#pragma unroll 1
    for (int t = 0; t < SEQ; ++t) {
        // Prefetch next unary value (consumed next iteration)
        if (lane == 0) {
            const int tn = (t + 1 < SEQ) ? (t + 1) : (SEQ - 1);
            unext = __ldg(unary + tn * NT + j);
        }

        // scores: s_i = alpha_i + tr[j][i]  (bit-identical to reference)
        float s[IPL];
#pragma unroll
        for (int k = 0; k < IPL; ++k) s[k] = a[k] + tr[k];

        // lane-local max (tree), then warp max via REDUX on orderable uint
        float m0 = fmaxf(fmaxf(s[0],  s[1]),  fmaxf(s[2],  s[3]));
        float m1 = fmaxf(fmaxf(s[4],  s[5]),  fmaxf(s[6],  s[7]));
        float m2 = fmaxf(fmaxf(s[8],  s[9]),  fmaxf(s[10], s[11]));
        float m3 = fmaxf(fmaxf(s[12], s[13]), fmaxf(s[14], s[15]));
        float m  = fmaxf(fmaxf(m0, m1), fmaxf(m2, m3));
        unsigned om = __reduce_max_sync(0xffffffffu, enc32(m));
        float vit = dec32(om);

        // Publish new alpha (vit + u_t[j]) into the other buffer
        if (lane == 0)
            __stcg(&g_alphas[(t + 1) & 1][j], vit + ucur);
        ucur = unext;

        __syncthreads();              // all 4 warps' stores done (CTA order)
        if (tid == 0) bar_arrive();   // cumulative release publishes them

        // --- barrier shadow: backpointer (exact equality, first index) ---
        unsigned mask = 0u;
#pragma unroll
        for (int k = 0; k < IPL; ++k) if (s[k] == vit) mask |= (1u << k);
        const unsigned bal = __ballot_sync(0xffffffffu, mask != 0u);
        const int leader = __ffs(bal) - 1;
        if (lane == leader)
            g_bp[t][j] = (unsigned short)(ibase + __ffs(mask) - 1);
        // -----------------------------------------------------------------

        nbar++;
        if (tid == 0) bar_wait(nbar);
        __syncthreads();

        // Reload alphas for next step (L2-only: other CTAs wrote them)
        {
            const float4* ap =
                reinterpret_cast<const float4*>(&g_alphas[(t + 1) & 1][ibase]);
#pragma unroll
            for (int q = 0; q < 4; ++q) {
                float4 v = __ldcg(ap + q);
                a[4*q+0]=v.x; a[4*q+1]=v.y; a[4*q+2]=v.z; a[4*q+3]=v.w;
            }
        }
    }

    // Terminal: alphas_final (in buffer 0 since SEQ is even) + tr[END_TAG,:]
    if (cta == 0) {
        __shared__ unsigned long long sh[TPB];
        unsigned long long best = 0ull;
#pragma unroll
        for (int q = 0; q < 4; ++q) {
            const int i = tid * 4 + q;
            float term = __ldcg(&g_alphas[0][i]) + __ldg(trans + END_TAG * NT + i);
            // larger value wins; on exact tie, smaller index wins (first-max)
            unsigned long long key =
                ((unsigned long long)enc32(term) << 32) | (unsigned)(NT - 1 - i);
            if (key > best) best = key;
        }
        sh[tid] = best;
        __syncthreads();
        if (tid == 0) {
            unsigned long long b = sh[0];
            for (int k = 1; k < TPB; ++k) if (sh[k] > b) b = sh[k];
            g_best = NT - 1 - (int)(b & 0xffffffffu);
            const float sc = dec32((unsigned)(b >> 32));
            if (out_size > SEQ) out[SEQ] = sc;   // (path, score) layout
        }
    }
}

// ---------------------------------------------------------------------------
// Traceback pass A: per-segment exit map for every possible entry tag.
// Segment s covers t in [s*SEGLEN, (s+1)*SEGLEN); entry tag lives at the top.
// ---------------------------------------------------------------------------
__global__ void viterbi_exits() {
    const int s = blockIdx.x;
    int cur = threadIdx.x;              // candidate entry tag
    const int tbase = s * SEGLEN;
    for (int t = tbase + SEGLEN - 1; t >= tbase; --t)
        cur = g_bp[t][cur];
    g_exit[s][threadIdx.x] = (unsigned short)cur;
}

// ---------------------------------------------------------------------------
// Traceback pass B (sequential compose) + C (parallel path write)
// ---------------------------------------------------------------------------
__global__ void viterbi_trace(float* __restrict__ out, int out_size) {
    __shared__ int entry[SEGS];
    const int tid = threadIdx.x;
    if (tid == 0) {
        int cur = g_best;               // path[SEQ-1]
        for (int s = SEGS - 1; s >= 0; --s) {
            entry[s] = cur;
            cur = g_exit[s][cur];
        }
    }
    __syncthreads();
    int cur = entry[tid];
    const int tbase = tid * SEGLEN;
    for (int t = tbase + SEGLEN - 1; t >= tbase; --t) {
        if (t < out_size) out[t] = (float)cur;
        cur = g_bp[t][cur];
    }
}

// ---------------------------------------------------------------------------
// Launch
// ---------------------------------------------------------------------------
extern "C" void kernel_launch(void* const* d_in, const int* in_sizes, int n_in,
                              void* d_out, int out_size) {
    const float* unary = (const float*)d_in[0];   // [SEQ,1,NT] f32
    const float* trans = (const float*)d_in[1];   // [1,NT,NT]  f32
    (void)in_sizes; (void)n_in;                   // lengths == SEQ, unused
    float* out = (float*)d_out;

    viterbi_reset<<<1, 1>>>();                    // barrier counter := 0
    viterbi_main <<<GRIDN, TPB>>>(unary, trans, out, out_size);
    viterbi_exits<<<SEGS, NT>>>();
    viterbi_trace<<<1, SEGS>>>(out, out_size);
}